// round 3
// baseline (speedup 1.0000x reference)
#include <cuda_runtime.h>

// Grouping: segment mean-pooling over sorted segment ids — single fused kernel.
//   feats: [B=8, S=8192, H=512] f32;  seg: [B, S] i32 sorted;  out: [B,G=1024,H] f32 (+counts tail)
//
// Grid = B * (S/TOK) CTAs. Chunk c of batch b owns groups g in (seg[cT-1], seg[(c+1)T-1]]
// (last chunk extended to G-1). This is a disjoint complete partition, every owned
// group STARTS inside the chunk, and its end lies within a 256-token lookahead window
// (global binary-search fallback for pathological groups). Boundaries are found by
// parallel adjacent-diff on the smem id window — no separate boundaries kernel.

#define BB 8
#define SS 8192
#define HH 512
#define GG 1024
#define H4 (HH / 4)       // 128 float4 per row == blockDim.x
#define TOK 64            // tokens owned per CTA
#define WIN 256           // id lookahead window
#define NCH (SS / TOK)    // 128 chunks per batch row

__global__ __launch_bounds__(128)
void group_mean_fused(const float4* __restrict__ feats4,
                      const int* __restrict__ seg,
                      float* __restrict__ out,
                      int write_counts)
{
    const int bc = blockIdx.x;
    const int b  = bc >> 7;            // / NCH
    const int c  = bc & (NCH - 1);     // % NCH
    const int t  = threadIdx.x;
    const int base = c * TOK;

    __shared__ int sid[WIN + 1];       // sid[0]=id at base-1 (or -1); sid[1+i]=id at base+i (GG sentinel past S)
    __shared__ int gstart[GG + 2];     // window-relative start pos, indexed by (g - lo)

    const int* __restrict__ srow = seg + b * SS;

    // ---- load id window ----
    for (int i = t; i < WIN; i += 128) {
        int idx = base + i;
        sid[1 + i] = (idx < SS) ? srow[idx] : GG;
    }
    if (t == 0) sid[0] = (base == 0) ? -1 : srow[base - 1];
    __syncthreads();

    const int lo = sid[0] + 1;
    int hi = sid[TOK];                         // id of last token in chunk
    if (c == NCH - 1) hi = GG - 1;             // last chunk owns trailing empty groups
    if (lo > hi) return;                       // chunk fully inside a group owned upstream

    // entry hi+1 may be uncovered if group hi extends past the window
    if (t == 0) gstart[hi - lo + 1] = -1;
    __syncthreads();

    // ---- parallel adjacent-diff: group g starts where ids cross g ----
    for (int i = t; i < WIN; i += 128) {
        int prev = sid[i];
        int cur  = sid[i + 1];
        int glo = max(prev + 1, lo);
        int ghi = min(cur, hi + 1);
        for (int g = glo; g <= ghi; ++g)
            gstart[g - lo] = i;
    }
    __syncthreads();

    // ---- stream each owned group ----
    const float4* __restrict__ fb = feats4 + (size_t)b * SS * H4 + t;
    float4* __restrict__ ob = (float4*)out + (size_t)b * GG * H4 + t;

    for (int g = lo; g <= hi; ++g) {
        const int start = base + gstart[g - lo];
        int ep = gstart[g - lo + 1];
        int end;
        if (ep >= 0) {
            end = base + ep;
        } else {
            // rare: group hi extends beyond window -> converged lower_bound of (hi+1)
            int l = base + WIN, h = SS;
            while (l < h) { int m = (l + h) >> 1; if (srow[m] <= g) l = m + 1; else h = m; }
            end = l;
        }
        const int n = end - start;

        float4 acc = make_float4(0.f, 0.f, 0.f, 0.f);
        const float4* __restrict__ p = fb + (size_t)start * H4;
        int s = 0;
        for (; s + 4 <= n; s += 4) {
            float4 v0 = p[(size_t)(s + 0) * H4];
            float4 v1 = p[(size_t)(s + 1) * H4];
            float4 v2 = p[(size_t)(s + 2) * H4];
            float4 v3 = p[(size_t)(s + 3) * H4];
            acc.x += (v0.x + v1.x) + (v2.x + v3.x);
            acc.y += (v0.y + v1.y) + (v2.y + v3.y);
            acc.z += (v0.z + v1.z) + (v2.z + v3.z);
            acc.w += (v0.w + v1.w) + (v2.w + v3.w);
        }
        for (; s < n; ++s) {
            float4 v = p[(size_t)s * H4];
            acc.x += v.x; acc.y += v.y; acc.z += v.z; acc.w += v.w;
        }

        const float inv = (n > 0) ? (1.0f / (float)n) : 0.0f;
        acc.x *= inv; acc.y *= inv; acc.z *= inv; acc.w *= inv;
        ob[(size_t)g * H4] = acc;

        if (write_counts && t == 0)
            out[(size_t)BB * GG * HH + b * GG + g] = (float)n;
    }
}

extern "C" void kernel_launch(void* const* d_in, const int* in_sizes, int n_in,
                              void* d_out, int out_size)
{
    const float4* feats4 = (const float4*)d_in[0];
    const int*    seg    = (const int*)d_in[1];
    float*        out    = (float*)d_out;

    const int grouped_elems = BB * GG * HH;
    const int write_counts  = (out_size >= grouped_elems + BB * GG) ? 1 : 0;

    group_mean_fused<<<BB * NCH, 128>>>(feats4, seg, out, write_counts);
}